// round 13
// baseline (speedup 1.0000x reference)
#include <cuda_runtime.h>
#include <cuda_bf16.h>
#include <math.h>
#include <stdint.h>

// ---------------- static problem sizes ----------------
#define NN  100000
#define EE  1600000
#define F0  512
#define D1  64
#define D2  256

// ---------------- device scratch ----------------
__device__ float g_dinv[NN];
__device__ int   g_cnt[NN];
__device__ int   g_rowstart[NN + 1];
__device__ int   g_cursor[NN];
__device__ int   g_csr[EE];
__device__ float g_wgt[EE];             // fp32 weights (aggz)
__device__ __nv_bfloat162 g_wgth[EE];   // packed bf16x2 weights (HFMA2 agg)
__device__ int   g_bsum[512];
__device__ __nv_bfloat16 g_xw1[(size_t)NN * D1];
__device__ __nv_bfloat16 g_h1 [(size_t)NN * D1];
__device__ float g_xw3[NN];

// ---------------- init: zero counters + xw3 + output ----------------
__global__ void init_kernel(float* out, int n) {
    int i = blockIdx.x * blockDim.x + threadIdx.x;
    if (i < n) { g_cnt[i] = 0; g_xw3[i] = 0.0f; }
    if (i == 0) out[0] = 0.0f;
}

__global__ void hist_kernel(const int* __restrict__ dst, int e) {
    int i = blockIdx.x * blockDim.x + threadIdx.x;
    if (i < e) atomicAdd(&g_cnt[dst[i]], 1);
}

// ---------------- dinv + per-block sums (fused) ----------------
__global__ void bsumdinv_kernel(int n) {
    __shared__ int wsum[8];
    int i = blockIdx.x * 256 + threadIdx.x;
    int v = (i < n) ? g_cnt[i] : 0;
    if (i < n) g_dinv[i] = rsqrtf((float)(v + 1));
    int s = v;
    #pragma unroll
    for (int o = 16; o; o >>= 1) s += __shfl_xor_sync(0xffffffffu, s, o);
    if ((threadIdx.x & 31) == 0) wsum[threadIdx.x >> 5] = s;
    __syncthreads();
    if (threadIdx.x == 0) {
        int t = 0;
        #pragma unroll
        for (int w = 0; w < 8; w++) t += wsum[w];
        g_bsum[blockIdx.x] = t;
    }
}

__global__ void bscan_kernel(int nb, int n) {
    __shared__ int s[512];
    int t = threadIdx.x;
    int orig = (t < nb) ? g_bsum[t] : 0;
    s[t] = orig;
    __syncthreads();
    #pragma unroll
    for (int o = 1; o < 512; o <<= 1) {
        int v = (t >= o) ? s[t - o] : 0;
        __syncthreads();
        s[t] += v;
        __syncthreads();
    }
    if (t < nb) g_bsum[t] = s[t] - orig;
    if (t == 0) g_rowstart[n] = s[511];
}

__global__ void rowstart_kernel(int n) {
    __shared__ int warp_off[8];
    int tid = threadIdx.x;
    int i = blockIdx.x * 256 + tid;
    int v = (i < n) ? g_cnt[i] : 0;
    int x = v;
    #pragma unroll
    for (int o = 1; o < 32; o <<= 1) {
        int t = __shfl_up_sync(0xffffffffu, x, o);
        if ((tid & 31) >= o) x += t;
    }
    if ((tid & 31) == 31) warp_off[tid >> 5] = x;
    __syncthreads();
    if (tid < 8) {
        int w = warp_off[tid];
        int y = w;
        #pragma unroll
        for (int o = 1; o < 8; o <<= 1) {
            int t = __shfl_up_sync(0xffu, y, o);
            if (tid >= o) y += t;
        }
        warp_off[tid] = y - w;
    }
    __syncthreads();
    if (i < n) {
        int rs = g_bsum[blockIdx.x] + x - v + warp_off[tid >> 5];
        g_rowstart[i] = rs;
        g_cursor[i] = rs;
    }
}

// fill CSR + edge weights (fp32 + packed bf16x2)
__global__ void fill_kernel(const int* __restrict__ src, const int* __restrict__ dst, int e) {
    int i = blockIdx.x * blockDim.x + threadIdx.x;
    if (i < e) {
        int s = src[i], d = dst[i];
        int p = atomicAdd(&g_cursor[d], 1);
        float w = g_dinv[s] * g_dinv[d];
        g_csr[p] = s;
        g_wgt[p] = w;
        g_wgth[p] = __float2bfloat162_rn(w);
    }
}

// ---------------- tensor-core helpers ----------------
__device__ __forceinline__ uint32_t smem_u32(const void* p) {
    return (uint32_t)__cvta_generic_to_shared(p);
}
__device__ __forceinline__ void ldsm_x4(uint32_t& r0, uint32_t& r1, uint32_t& r2, uint32_t& r3, uint32_t a) {
    asm volatile("ldmatrix.sync.aligned.m8n8.x4.shared.b16 {%0,%1,%2,%3}, [%4];\n"
                 : "=r"(r0), "=r"(r1), "=r"(r2), "=r"(r3) : "r"(a));
}
__device__ __forceinline__ void ldsm_x4_t(uint32_t& r0, uint32_t& r1, uint32_t& r2, uint32_t& r3, uint32_t a) {
    asm volatile("ldmatrix.sync.aligned.m8n8.x4.trans.shared.b16 {%0,%1,%2,%3}, [%4];\n"
                 : "=r"(r0), "=r"(r1), "=r"(r2), "=r"(r3) : "r"(a));
}
__device__ __forceinline__ void mma_bf16(float* c, const uint32_t* a, const uint32_t* b) {
    asm volatile(
        "mma.sync.aligned.m16n8k16.row.col.f32.bf16.bf16.f32 "
        "{%0,%1,%2,%3}, {%4,%5,%6,%7}, {%8,%9}, {%0,%1,%2,%3};\n"
        : "+f"(c[0]), "+f"(c[1]), "+f"(c[2]), "+f"(c[3])
        : "r"(a[0]), "r"(a[1]), "r"(a[2]), "r"(a[3]), "r"(b[0]), "r"(b[1]));
}

// ---------------- gemm1: xw1 = x @ W1 (fp32 in, bf16 out), double-buffered smem ----
__global__ void __launch_bounds__(256)
gemm1_kernel(const float* __restrict__ A, const float* __restrict__ B, int M) {
    __shared__ __align__(16) __nv_bfloat16 As[2][128][72];
    __shared__ __align__(16) __nv_bfloat16 Bs[2][64][72];
    const int tid = threadIdx.x, lane = tid & 31, w = tid >> 5;
    const int wm = (w & 3) * 32, wn = (w >> 2) * 32;
    const int row0 = blockIdx.y * 128;

    float acc[2][4][4];
    #pragma unroll
    for (int mt = 0; mt < 2; mt++)
        #pragma unroll
        for (int nt = 0; nt < 4; nt++)
            #pragma unroll
            for (int r = 0; r < 4; r++) acc[mt][nt][r] = 0.0f;

    float4 a_f[8], b_f[4];
    auto load_regs = [&](int k0) {
        #pragma unroll
        for (int i = 0; i < 8; i++) {
            int idx = tid + i * 256;
            int r = idx >> 4, cq = idx & 15;
            int gr = row0 + r;
            a_f[i] = (gr < M) ? *(const float4*)&A[(size_t)gr * F0 + k0 + cq * 4]
                              : make_float4(0.f, 0.f, 0.f, 0.f);
        }
        #pragma unroll
        for (int i = 0; i < 4; i++) {
            int idx = tid + i * 256;
            int r = idx >> 4, cq = idx & 15;
            b_f[i] = *(const float4*)&B[(size_t)(k0 + r) * D1 + cq * 4];
        }
    };
    auto store_smem = [&](int buf) {
        #pragma unroll
        for (int i = 0; i < 8; i++) {
            int idx = tid + i * 256;
            int r = idx >> 4, cq = idx & 15;
            *(__nv_bfloat162*)&As[buf][r][cq * 4]     = __floats2bfloat162_rn(a_f[i].x, a_f[i].y);
            *(__nv_bfloat162*)&As[buf][r][cq * 4 + 2] = __floats2bfloat162_rn(a_f[i].z, a_f[i].w);
        }
        #pragma unroll
        for (int i = 0; i < 4; i++) {
            int idx = tid + i * 256;
            int r = idx >> 4, cq = idx & 15;
            *(__nv_bfloat162*)&Bs[buf][r][cq * 4]     = __floats2bfloat162_rn(b_f[i].x, b_f[i].y);
            *(__nv_bfloat162*)&Bs[buf][r][cq * 4 + 2] = __floats2bfloat162_rn(b_f[i].z, b_f[i].w);
        }
    };

    load_regs(0);
    store_smem(0);
    __syncthreads();
    int cur = 0;
    for (int k0 = 0; k0 < F0; k0 += 64) {
        bool more = (k0 + 64 < F0);
        if (more) load_regs(k0 + 64);
        #pragma unroll
        for (int ks = 0; ks < 4; ks++) {
            uint32_t a[2][4];
            #pragma unroll
            for (int mt = 0; mt < 2; mt++) {
                int rrow = wm + mt * 16 + (lane & 7) + ((lane >> 3) & 1) * 8;
                int ccol = ks * 16 + (lane >> 4) * 8;
                ldsm_x4(a[mt][0], a[mt][1], a[mt][2], a[mt][3], smem_u32(&As[cur][rrow][ccol]));
            }
            uint32_t b[4][2];
            #pragma unroll
            for (int pr = 0; pr < 2; pr++) {
                int kk = ks * 16 + ((lane >> 3) & 1) * 8 + (lane & 7);
                int nn = wn + pr * 16 + (lane >> 4) * 8;
                uint32_t r0, r1, r2, r3;
                ldsm_x4_t(r0, r1, r2, r3, smem_u32(&Bs[cur][kk][nn]));
                b[pr * 2][0] = r0; b[pr * 2][1] = r1;
                b[pr * 2 + 1][0] = r2; b[pr * 2 + 1][1] = r3;
            }
            #pragma unroll
            for (int mt = 0; mt < 2; mt++)
                #pragma unroll
                for (int nt = 0; nt < 4; nt++)
                    mma_bf16(acc[mt][nt], a[mt], b[nt]);
        }
        if (more) store_smem(cur ^ 1);
        __syncthreads();
        cur ^= 1;
    }
    #pragma unroll
    for (int mt = 0; mt < 2; mt++) {
        int r_lo = row0 + wm + mt * 16 + (lane >> 2);
        #pragma unroll
        for (int nt = 0; nt < 4; nt++) {
            int c = wn + nt * 8 + (lane & 3) * 2;
            if (r_lo < M)
                *(__nv_bfloat162*)&g_xw1[(size_t)r_lo * D1 + c] =
                    __floats2bfloat162_rn(acc[mt][nt][0], acc[mt][nt][1]);
            if (r_lo + 8 < M)
                *(__nv_bfloat162*)&g_xw1[(size_t)(r_lo + 8) * D1 + c] =
                    __floats2bfloat162_rn(acc[mt][nt][2], acc[mt][nt][3]);
        }
    }
}

// ---------------- 64-dim gather core: packed bf16x2 HFMA2 accumulation ----------
// acc: 4 x __nv_bfloat162 (8 bf16 values per lane)
__device__ __forceinline__ void agg_row64_h(__nv_bfloat162* acc, const uint4* in, int sub,
                                            int s0, int s1) {
    for (int j = s0; j < s1; j++) {
        int s = __ldg(&g_csr[j]);
        __nv_bfloat162 w2 = g_wgth[j];
        uint4 v = in[(size_t)s * 8 + sub];
        const __nv_bfloat162* p = (const __nv_bfloat162*)&v;
        #pragma unroll
        for (int q = 0; q < 4; q++)
            acc[q] = __hfma2(w2, p[q], acc[q]);
    }
}

// ---------------- layer 1 aggregation: h1 = relu(agg(xw1) + b1) -----------------
__global__ void agg1_kernel(const float* __restrict__ bias, int n) {
    int g = blockIdx.x * blockDim.x + threadIdx.x;
    int node = g >> 3;
    int sub  = g & 7;
    if (node >= n) return;
    const uint4* in = (const uint4*)g_xw1;
    float di = g_dinv[node];
    __nv_bfloat162 w02 = __float2bfloat162_rn(di * di);
    __nv_bfloat162 acc[4];
    {
        uint4 v = in[(size_t)node * 8 + sub];
        const __nv_bfloat162* p = (const __nv_bfloat162*)&v;
        #pragma unroll
        for (int q = 0; q < 4; q++)
            acc[q] = __hmul2(w02, p[q]);
    }
    agg_row64_h(acc, in, sub, g_rowstart[node], g_rowstart[node + 1]);
    // epilogue in fp32: + bias, relu (per node, cheap)
    uint4 o;
    __nv_bfloat162* po = (__nv_bfloat162*)&o;
    #pragma unroll
    for (int q = 0; q < 4; q++) {
        float2 f = __bfloat1622float2(acc[q]);
        float v0 = fmaxf(f.x + bias[sub * 8 + q * 2],     0.0f);
        float v1 = fmaxf(f.y + bias[sub * 8 + q * 2 + 1], 0.0f);
        po[q] = __floats2bfloat162_rn(v0, v1);
    }
    ((uint4*)g_h1)[(size_t)node * 8 + sub] = o;
}

// ---------------- fused layer 2+3: agg(h1) -> @W2+b2, relu, dot W3 -> xw3 --------
__global__ void __launch_bounds__(256)
fused_l2_kernel(const float* __restrict__ W2, const float* __restrict__ b2,
                const float* __restrict__ W3, int n) {
    __shared__ __align__(16) __nv_bfloat16 As[128][72];
    __shared__ __align__(16) __nv_bfloat16 Bs[64][72];
    const int tid = threadIdx.x, lane = tid & 31, w = tid >> 5;
    const int wm = (w & 3) * 32, wn = (w >> 2) * 32;
    const int row0 = blockIdx.x * 128;

    // ---- prologue: aggregate 128 rows of h1 into As (bf16x2 HFMA2, no converts) ----
    const uint4* in = (const uint4*)g_h1;
    #pragma unroll
    for (int it = 0; it < 4; it++) {
        int r = (tid >> 3) + it * 32;
        int sub = tid & 7;
        int node = row0 + r;
        __nv_bfloat162 acc[4];
        __nv_bfloat162 z2 = __float2bfloat162_rn(0.0f);
        acc[0] = acc[1] = acc[2] = acc[3] = z2;
        if (node < n) {
            float di = g_dinv[node];
            __nv_bfloat162 w02 = __float2bfloat162_rn(di * di);
            uint4 v = in[(size_t)node * 8 + sub];
            const __nv_bfloat162* p = (const __nv_bfloat162*)&v;
            #pragma unroll
            for (int q = 0; q < 4; q++)
                acc[q] = __hmul2(w02, p[q]);
            agg_row64_h(acc, in, sub, g_rowstart[node], g_rowstart[node + 1]);
        }
        uint4 o;
        __nv_bfloat162* po = (__nv_bfloat162*)&o;
        #pragma unroll
        for (int q = 0; q < 4; q++) po[q] = acc[q];
        *(uint4*)&As[r][sub * 8] = o;
    }
    __syncthreads();

    // ---- hoist A fragments ----
    uint32_t afrag[4][2][4];
    #pragma unroll
    for (int ks = 0; ks < 4; ks++) {
        #pragma unroll
        for (int mt = 0; mt < 2; mt++) {
            int rrow = wm + mt * 16 + (lane & 7) + ((lane >> 3) & 1) * 8;
            int ccol = ks * 16 + (lane >> 4) * 8;
            ldsm_x4(afrag[ks][mt][0], afrag[ks][mt][1], afrag[ks][mt][2], afrag[ks][mt][3],
                    smem_u32(&As[rrow][ccol]));
        }
    }

    float rs0[2], rs1[2];
    rs0[0] = rs0[1] = rs1[0] = rs1[1] = 0.0f;

    for (int ch = 0; ch < 4; ch++) {
        int cols0 = ch * 64;
        #pragma unroll
        for (int i = 0; i < 4; i++) {
            int idx = tid + i * 256;
            int r = idx >> 4, cq = idx & 15;
            float4 v = *(const float4*)&W2[(size_t)r * D2 + cols0 + cq * 4];
            *(__nv_bfloat162*)&Bs[r][cq * 4]     = __floats2bfloat162_rn(v.x, v.y);
            *(__nv_bfloat162*)&Bs[r][cq * 4 + 2] = __floats2bfloat162_rn(v.z, v.w);
        }
        __syncthreads();

        float acc[2][4][4];
        #pragma unroll
        for (int mt = 0; mt < 2; mt++)
            #pragma unroll
            for (int nt = 0; nt < 4; nt++)
                #pragma unroll
                for (int r = 0; r < 4; r++) acc[mt][nt][r] = 0.0f;

        #pragma unroll
        for (int ks = 0; ks < 4; ks++) {
            uint32_t b[4][2];
            #pragma unroll
            for (int pr = 0; pr < 2; pr++) {
                int kk = ks * 16 + ((lane >> 3) & 1) * 8 + (lane & 7);
                int nn = wn + pr * 16 + (lane >> 4) * 8;
                uint32_t r0, r1, r2, r3;
                ldsm_x4_t(r0, r1, r2, r3, smem_u32(&Bs[kk][nn]));
                b[pr * 2][0] = r0; b[pr * 2][1] = r1;
                b[pr * 2 + 1][0] = r2; b[pr * 2 + 1][1] = r3;
            }
            #pragma unroll
            for (int mt = 0; mt < 2; mt++)
                #pragma unroll
                for (int nt = 0; nt < 4; nt++)
                    mma_bf16(acc[mt][nt], afrag[ks][mt], b[nt]);
        }
        #pragma unroll
        for (int mt = 0; mt < 2; mt++) {
            #pragma unroll
            for (int nt = 0; nt < 4; nt++) {
                int c = cols0 + wn + nt * 8 + (lane & 3) * 2;
                float bb0 = b2[c], bb1 = b2[c + 1];
                float w30 = W3[c], w31 = W3[c + 1];
                float v0 = fmaxf(acc[mt][nt][0] + bb0, 0.f);
                float v1 = fmaxf(acc[mt][nt][1] + bb1, 0.f);
                float v2 = fmaxf(acc[mt][nt][2] + bb0, 0.f);
                float v3 = fmaxf(acc[mt][nt][3] + bb1, 0.f);
                rs0[mt] = fmaf(v0, w30, fmaf(v1, w31, rs0[mt]));
                rs1[mt] = fmaf(v2, w30, fmaf(v3, w31, rs1[mt]));
            }
        }
        __syncthreads();
    }

    #pragma unroll
    for (int mt = 0; mt < 2; mt++) {
        #pragma unroll
        for (int o = 1; o < 4; o <<= 1) {
            rs0[mt] += __shfl_xor_sync(0xffffffffu, rs0[mt], o);
            rs1[mt] += __shfl_xor_sync(0xffffffffu, rs1[mt], o);
        }
    }
    if ((lane & 3) == 0) {
        #pragma unroll
        for (int mt = 0; mt < 2; mt++) {
            int r_lo = row0 + wm + mt * 16 + (lane >> 2);
            if (r_lo < n)     atomicAdd(&g_xw3[r_lo], rs0[mt]);
            if (r_lo + 8 < n) atomicAdd(&g_xw3[r_lo + 8], rs1[mt]);
        }
    }
}

// ---------------- scalar aggregation of xw3 + fused BCE loss (fp32) ----------------
__global__ void aggz_loss_kernel(const float* __restrict__ y, const float* __restrict__ b3,
                                 float* __restrict__ out, int n) {
    int i = blockIdx.x * blockDim.x + threadIdx.x;
    float l = 0.0f;
    if (i < n) {
        float di = g_dinv[i];
        float acc = di * di * g_xw3[i];
        int s1 = g_rowstart[i + 1];
        for (int j = g_rowstart[i]; j < s1; j++) {
            acc = fmaf(__ldg(&g_wgt[j]), g_xw3[__ldg(&g_csr[j])], acc);
        }
        float z = acc + b3[0];
        float sp = fmaxf(z, 0.0f) + log1pf(expf(-fabsf(z)));
        l = sp - y[i] * z;
    }
    __shared__ float red[256];
    red[threadIdx.x] = l;
    __syncthreads();
    #pragma unroll
    for (int o = 128; o; o >>= 1) {
        if (threadIdx.x < o) red[threadIdx.x] += red[threadIdx.x + o];
        __syncthreads();
    }
    if (threadIdx.x == 0) atomicAdd(out, red[0] * (1.0f / (float)n));
}

// ---------------- launch ----------------
extern "C" void kernel_launch(void* const* d_in, const int* in_sizes, int n_in,
                              void* d_out, int out_size) {
    const float* x   = (const float*)d_in[0];
    const int*   ei  = (const int*)d_in[1];
    const float* y   = (const float*)d_in[2];
    const float* W1  = (const float*)d_in[3];
    const float* b1  = (const float*)d_in[4];
    const float* W2  = (const float*)d_in[5];
    const float* b2  = (const float*)d_in[6];
    const float* W3  = (const float*)d_in[7];
    const float* b3  = (const float*)d_in[8];
    float* out = (float*)d_out;

    int n = in_sizes[0] / F0;      // 100000
    int e = in_sizes[1] / 2;       // 1600000
    const int* src = ei;
    const int* dst = ei + e;

    static cudaStream_t s2 = nullptr;
    static cudaEvent_t evA = nullptr, evB = nullptr;
    if (!s2) {
        cudaStreamCreateWithFlags(&s2, cudaStreamNonBlocking);
        cudaEventCreateWithFlags(&evA, cudaEventDisableTiming);
        cudaEventCreateWithFlags(&evB, cudaEventDisableTiming);
    }

    int nb = (n + 255) / 256;
    int nblk = (n + 127) / 128;    // 782

    // fork: gemm1 (x @ W1, independent of graph structure) on s2
    cudaEventRecord(evA, 0);
    cudaStreamWaitEvent(s2, evA, 0);
    gemm1_kernel<<<dim3(1, nblk), 256, 0, s2>>>(x, W1, n);
    cudaEventRecord(evB, s2);

    // stream 0: graph structure build
    init_kernel<<<nb, 256>>>(out, n);
    hist_kernel<<<(e + 255) / 256, 256>>>(dst, e);
    bsumdinv_kernel<<<nb, 256>>>(n);
    bscan_kernel<<<1, 512>>>(nb, n);
    rowstart_kernel<<<nb, 256>>>(n);
    fill_kernel<<<(e + 255) / 256, 256>>>(src, dst, e);

    // join
    cudaStreamWaitEvent(0, evB, 0);

    // layer 1 aggregation (fused bias + relu)
    agg1_kernel<<<(n * 8 + 255) / 256, 256>>>(b1, n);

    // fused layer 2 + 3 front: agg(h1) @ W2 + b2, relu, dot W3 -> g_xw3
    fused_l2_kernel<<<nblk, 256>>>(W2, b2, W3, n);

    // final: scalar aggregation + BCE loss
    aggz_loss_kernel<<<(n + 255) / 256, 256>>>(y, b3, out, n);
}

// round 15
// speedup vs baseline: 1.1209x; 1.1209x over previous
#include <cuda_runtime.h>
#include <cuda_bf16.h>
#include <math.h>
#include <stdint.h>

// ---------------- static problem sizes ----------------
#define NN  100000
#define EE  1600000
#define F0  512
#define D1  64
#define D2  256

// ---------------- device scratch ----------------
__device__ float g_dinv[NN];
__device__ int   g_cnt[NN];
__device__ int   g_rowstart[NN];
__device__ int   g_cursor[NN];
__device__ int   g_csr[EE];
__device__ int   g_edgetot;
__device__ __nv_bfloat16 g_xw1[(size_t)NN * D1];
__device__ __nv_bfloat16 g_h1 [(size_t)NN * D1];
__device__ float g_xw3[NN];

// ---------------- init: zero counters + xw3 + output ----------------
__global__ void init_kernel(float* out, int n) {
    int i = blockIdx.x * blockDim.x + threadIdx.x;
    if (i < n) { g_cnt[i] = 0; g_xw3[i] = 0.0f; }
    if (i == 0) { out[0] = 0.0f; g_edgetot = 0; }
}

__global__ void hist_kernel(const int* __restrict__ dst, int e) {
    int i = blockIdx.x * blockDim.x + threadIdx.x;
    if (i < e) atomicAdd(&g_cnt[dst[i]], 1);
}

// ---------------- makecsr: dinv + segment allocation via warp-aggregated atomic ----
// Segments need not be in node order: row end = rowstart[i] + cnt[i].
__global__ void makecsr_kernel(int n) {
    int i = blockIdx.x * 256 + threadIdx.x;
    int lane = threadIdx.x & 31;
    int v = (i < n) ? g_cnt[i] : 0;
    if (i < n) g_dinv[i] = rsqrtf((float)(v + 1));
    int x = v;
    #pragma unroll
    for (int o = 1; o < 32; o <<= 1) {
        int t = __shfl_up_sync(0xffffffffu, x, o);
        if (lane >= o) x += t;
    }
    int wsum = __shfl_sync(0xffffffffu, x, 31);
    int base = 0;
    if (lane == 31) base = atomicAdd(&g_edgetot, wsum);
    base = __shfl_sync(0xffffffffu, base, 31);
    if (i < n) {
        int rs = base + x - v;
        g_rowstart[i] = rs;
        g_cursor[i] = rs;
    }
}

__global__ void fill_kernel(const int* __restrict__ src, const int* __restrict__ dst, int e) {
    int i = blockIdx.x * blockDim.x + threadIdx.x;
    if (i < e) {
        int p = atomicAdd(&g_cursor[dst[i]], 1);
        g_csr[p] = src[i];
    }
}

// ---------------- tensor-core helpers ----------------
__device__ __forceinline__ uint32_t smem_u32(const void* p) {
    return (uint32_t)__cvta_generic_to_shared(p);
}
__device__ __forceinline__ void ldsm_x4(uint32_t& r0, uint32_t& r1, uint32_t& r2, uint32_t& r3, uint32_t a) {
    asm volatile("ldmatrix.sync.aligned.m8n8.x4.shared.b16 {%0,%1,%2,%3}, [%4];\n"
                 : "=r"(r0), "=r"(r1), "=r"(r2), "=r"(r3) : "r"(a));
}
__device__ __forceinline__ void ldsm_x4_t(uint32_t& r0, uint32_t& r1, uint32_t& r2, uint32_t& r3, uint32_t a) {
    asm volatile("ldmatrix.sync.aligned.m8n8.x4.trans.shared.b16 {%0,%1,%2,%3}, [%4];\n"
                 : "=r"(r0), "=r"(r1), "=r"(r2), "=r"(r3) : "r"(a));
}
__device__ __forceinline__ void mma_bf16(float* c, const uint32_t* a, const uint32_t* b) {
    asm volatile(
        "mma.sync.aligned.m16n8k16.row.col.f32.bf16.bf16.f32 "
        "{%0,%1,%2,%3}, {%4,%5,%6,%7}, {%8,%9}, {%0,%1,%2,%3};\n"
        : "+f"(c[0]), "+f"(c[1]), "+f"(c[2]), "+f"(c[3])
        : "r"(a[0]), "r"(a[1]), "r"(a[2]), "r"(a[3]), "r"(b[0]), "r"(b[1]));
}

// ---------------- gemm1: xw1 = x @ W1 (fp32 in, bf16 out), double-buffered smem ----
// (R4 known-good version.)
__global__ void __launch_bounds__(256)
gemm1_kernel(const float* __restrict__ A, const float* __restrict__ B, int M) {
    __shared__ __align__(16) __nv_bfloat16 As[2][128][72];
    __shared__ __align__(16) __nv_bfloat16 Bs[2][64][72];
    const int tid = threadIdx.x, lane = tid & 31, w = tid >> 5;
    const int wm = (w & 3) * 32, wn = (w >> 2) * 32;
    const int row0 = blockIdx.y * 128;

    float acc[2][4][4];
    #pragma unroll
    for (int mt = 0; mt < 2; mt++)
        #pragma unroll
        for (int nt = 0; nt < 4; nt++)
            #pragma unroll
            for (int r = 0; r < 4; r++) acc[mt][nt][r] = 0.0f;

    float4 a_f[8], b_f[4];
    auto load_regs = [&](int k0) {
        #pragma unroll
        for (int i = 0; i < 8; i++) {
            int idx = tid + i * 256;
            int r = idx >> 4, cq = idx & 15;
            int gr = row0 + r;
            a_f[i] = (gr < M) ? *(const float4*)&A[(size_t)gr * F0 + k0 + cq * 4]
                              : make_float4(0.f, 0.f, 0.f, 0.f);
        }
        #pragma unroll
        for (int i = 0; i < 4; i++) {
            int idx = tid + i * 256;
            int r = idx >> 4, cq = idx & 15;
            b_f[i] = *(const float4*)&B[(size_t)(k0 + r) * D1 + cq * 4];
        }
    };
    auto store_smem = [&](int buf) {
        #pragma unroll
        for (int i = 0; i < 8; i++) {
            int idx = tid + i * 256;
            int r = idx >> 4, cq = idx & 15;
            *(__nv_bfloat162*)&As[buf][r][cq * 4]     = __floats2bfloat162_rn(a_f[i].x, a_f[i].y);
            *(__nv_bfloat162*)&As[buf][r][cq * 4 + 2] = __floats2bfloat162_rn(a_f[i].z, a_f[i].w);
        }
        #pragma unroll
        for (int i = 0; i < 4; i++) {
            int idx = tid + i * 256;
            int r = idx >> 4, cq = idx & 15;
            *(__nv_bfloat162*)&Bs[buf][r][cq * 4]     = __floats2bfloat162_rn(b_f[i].x, b_f[i].y);
            *(__nv_bfloat162*)&Bs[buf][r][cq * 4 + 2] = __floats2bfloat162_rn(b_f[i].z, b_f[i].w);
        }
    };

    load_regs(0);
    store_smem(0);
    __syncthreads();
    int cur = 0;
    for (int k0 = 0; k0 < F0; k0 += 64) {
        bool more = (k0 + 64 < F0);
        if (more) load_regs(k0 + 64);
        #pragma unroll
        for (int ks = 0; ks < 4; ks++) {
            uint32_t a[2][4];
            #pragma unroll
            for (int mt = 0; mt < 2; mt++) {
                int rrow = wm + mt * 16 + (lane & 7) + ((lane >> 3) & 1) * 8;
                int ccol = ks * 16 + (lane >> 4) * 8;
                ldsm_x4(a[mt][0], a[mt][1], a[mt][2], a[mt][3], smem_u32(&As[cur][rrow][ccol]));
            }
            uint32_t b[4][2];
            #pragma unroll
            for (int pr = 0; pr < 2; pr++) {
                int kk = ks * 16 + ((lane >> 3) & 1) * 8 + (lane & 7);
                int nn = wn + pr * 16 + (lane >> 4) * 8;
                uint32_t r0, r1, r2, r3;
                ldsm_x4_t(r0, r1, r2, r3, smem_u32(&Bs[cur][kk][nn]));
                b[pr * 2][0] = r0; b[pr * 2][1] = r1;
                b[pr * 2 + 1][0] = r2; b[pr * 2 + 1][1] = r3;
            }
            #pragma unroll
            for (int mt = 0; mt < 2; mt++)
                #pragma unroll
                for (int nt = 0; nt < 4; nt++)
                    mma_bf16(acc[mt][nt], a[mt], b[nt]);
        }
        if (more) store_smem(cur ^ 1);
        __syncthreads();
        cur ^= 1;
    }
    #pragma unroll
    for (int mt = 0; mt < 2; mt++) {
        int r_lo = row0 + wm + mt * 16 + (lane >> 2);
        #pragma unroll
        for (int nt = 0; nt < 4; nt++) {
            int c = wn + nt * 8 + (lane & 3) * 2;
            if (r_lo < M)
                *(__nv_bfloat162*)&g_xw1[(size_t)r_lo * D1 + c] =
                    __floats2bfloat162_rn(acc[mt][nt][0], acc[mt][nt][1]);
            if (r_lo + 8 < M)
                *(__nv_bfloat162*)&g_xw1[(size_t)(r_lo + 8) * D1 + c] =
                    __floats2bfloat162_rn(acc[mt][nt][2], acc[mt][nt][3]);
        }
    }
}

// ---------------- 64-dim gather-FMA core (R4 style: fp32 accum, dinv loads) -------
__device__ __forceinline__ void agg_row64(float* acc, const uint4* in, int sub,
                                          float di, int s0, int s1) {
    for (int j = s0; j < s1; j++) {
        int s = __ldg(&g_csr[j]);
        float wgt = g_dinv[s] * di;
        uint4 v = in[(size_t)s * 8 + sub];
        const uint32_t* p = (const uint32_t*)&v;
        #pragma unroll
        for (int q = 0; q < 4; q++) {
            float2 f = __bfloat1622float2(*(const __nv_bfloat162*)&p[q]);
            acc[q * 2]     = fmaf(wgt, f.x, acc[q * 2]);
            acc[q * 2 + 1] = fmaf(wgt, f.y, acc[q * 2 + 1]);
        }
    }
}

// ---------------- layer 1 aggregation: h1 = relu(agg(xw1) + b1), bf16 ----------------
__global__ void agg1_kernel(const float* __restrict__ bias, int n) {
    int g = blockIdx.x * blockDim.x + threadIdx.x;
    int node = g >> 3;
    int sub  = g & 7;
    if (node >= n) return;
    const uint4* in = (const uint4*)g_xw1;
    float di = g_dinv[node];
    float w0 = di * di;
    float acc[8];
    {
        uint4 v = in[(size_t)node * 8 + sub];
        const uint32_t* p = (const uint32_t*)&v;
        #pragma unroll
        for (int q = 0; q < 4; q++) {
            float2 f = __bfloat1622float2(*(const __nv_bfloat162*)&p[q]);
            acc[q * 2]     = f.x * w0;
            acc[q * 2 + 1] = f.y * w0;
        }
    }
    int s0 = g_rowstart[node];
    agg_row64(acc, in, sub, di, s0, s0 + g_cnt[node]);
    uint4 o;
    uint32_t* po = (uint32_t*)&o;
    #pragma unroll
    for (int q = 0; q < 4; q++) {
        float v0 = fmaxf(acc[q * 2]     + bias[sub * 8 + q * 2],     0.0f);
        float v1 = fmaxf(acc[q * 2 + 1] + bias[sub * 8 + q * 2 + 1], 0.0f);
        *(__nv_bfloat162*)&po[q] = __floats2bfloat162_rn(v0, v1);
    }
    ((uint4*)g_h1)[(size_t)node * 8 + sub] = o;
}

// ---------------- fused layer 2+3: agg(h1) -> @W2+b2, relu, dot W3 -> xw3 --------
// Whole W2 staged once in dynamic smem; ONE barrier between prologue and MMA.
#define FL2_AS_ROWS 128
#define FL2_AS_STRIDE 72
#define FL2_BS_STRIDE 264
#define FL2_SMEM (FL2_AS_ROWS * FL2_AS_STRIDE * 2 + 64 * FL2_BS_STRIDE * 2)  // 52224
__global__ void __launch_bounds__(256)
fused_l2_kernel(const float* __restrict__ W2, const float* __restrict__ b2,
                const float* __restrict__ W3, int n) {
    extern __shared__ char dynsmem[];
    __nv_bfloat16 (*As)[FL2_AS_STRIDE] = (__nv_bfloat16 (*)[FL2_AS_STRIDE])dynsmem;
    __nv_bfloat16 (*Bs)[FL2_BS_STRIDE] =
        (__nv_bfloat16 (*)[FL2_BS_STRIDE])(dynsmem + FL2_AS_ROWS * FL2_AS_STRIDE * 2);
    const int tid = threadIdx.x, lane = tid & 31, w = tid >> 5;
    const int wm = (w & 3) * 32, wn = (w >> 2) * 32;
    const int row0 = blockIdx.x * 128;

    // ---- stage ALL of W2 (64 x 256 fp32 -> bf16) ----
    #pragma unroll
    for (int i = 0; i < 16; i++) {
        int idx = tid + i * 256;
        int r = idx >> 6, cq = idx & 63;
        float4 v = *(const float4*)&W2[(size_t)r * D2 + cq * 4];
        *(__nv_bfloat162*)&Bs[r][cq * 4]     = __floats2bfloat162_rn(v.x, v.y);
        *(__nv_bfloat162*)&Bs[r][cq * 4 + 2] = __floats2bfloat162_rn(v.z, v.w);
    }

    // ---- prologue: aggregate 128 rows of h1 into As ----
    const uint4* in = (const uint4*)g_h1;
    #pragma unroll
    for (int it = 0; it < 4; it++) {
        int r = (tid >> 3) + it * 32;
        int sub = tid & 7;
        int node = row0 + r;
        float acc[8];
        #pragma unroll
        for (int q = 0; q < 8; q++) acc[q] = 0.0f;
        if (node < n) {
            float di = g_dinv[node];
            float w0 = di * di;
            uint4 v = in[(size_t)node * 8 + sub];
            const uint32_t* p = (const uint32_t*)&v;
            #pragma unroll
            for (int q = 0; q < 4; q++) {
                float2 f = __bfloat1622float2(*(const __nv_bfloat162*)&p[q]);
                acc[q * 2]     = f.x * w0;
                acc[q * 2 + 1] = f.y * w0;
            }
            int s0 = g_rowstart[node];
            agg_row64(acc, in, sub, di, s0, s0 + g_cnt[node]);
        }
        uint4 o;
        uint32_t* po = (uint32_t*)&o;
        #pragma unroll
        for (int q = 0; q < 4; q++)
            *(__nv_bfloat162*)&po[q] = __floats2bfloat162_rn(acc[q * 2], acc[q * 2 + 1]);
        *(uint4*)&As[r][sub * 8] = o;
    }
    __syncthreads();   // the ONLY barrier

    // ---- hoist A fragments ----
    uint32_t afrag[4][2][4];
    #pragma unroll
    for (int ks = 0; ks < 4; ks++) {
        #pragma unroll
        for (int mt = 0; mt < 2; mt++) {
            int rrow = wm + mt * 16 + (lane & 7) + ((lane >> 3) & 1) * 8;
            int ccol = ks * 16 + (lane >> 4) * 8;
            ldsm_x4(afrag[ks][mt][0], afrag[ks][mt][1], afrag[ks][mt][2], afrag[ks][mt][3],
                    smem_u32(&As[rrow][ccol]));
        }
    }

    float rs0[2], rs1[2];
    rs0[0] = rs0[1] = rs1[0] = rs1[1] = 0.0f;

    #pragma unroll
    for (int ch = 0; ch < 4; ch++) {
        int cols0 = ch * 64;
        float acc[2][4][4];
        #pragma unroll
        for (int mt = 0; mt < 2; mt++)
            #pragma unroll
            for (int nt = 0; nt < 4; nt++)
                #pragma unroll
                for (int r = 0; r < 4; r++) acc[mt][nt][r] = 0.0f;

        #pragma unroll
        for (int ks = 0; ks < 4; ks++) {
            uint32_t b[4][2];
            #pragma unroll
            for (int pr = 0; pr < 2; pr++) {
                int kk = ks * 16 + ((lane >> 3) & 1) * 8 + (lane & 7);
                int nn = cols0 + wn + pr * 16 + (lane >> 4) * 8;
                uint32_t r0, r1, r2, r3;
                ldsm_x4_t(r0, r1, r2, r3, smem_u32(&Bs[kk][nn]));
                b[pr * 2][0] = r0; b[pr * 2][1] = r1;
                b[pr * 2 + 1][0] = r2; b[pr * 2 + 1][1] = r3;
            }
            #pragma unroll
            for (int mt = 0; mt < 2; mt++)
                #pragma unroll
                for (int nt = 0; nt < 4; nt++)
                    mma_bf16(acc[mt][nt], afrag[ks][mt], b[nt]);
        }
        #pragma unroll
        for (int mt = 0; mt < 2; mt++) {
            #pragma unroll
            for (int nt = 0; nt < 4; nt++) {
                int c = cols0 + wn + nt * 8 + (lane & 3) * 2;
                float bb0 = b2[c], bb1 = b2[c + 1];
                float w30 = W3[c], w31 = W3[c + 1];
                float v0 = fmaxf(acc[mt][nt][0] + bb0, 0.f);
                float v1 = fmaxf(acc[mt][nt][1] + bb1, 0.f);
                float v2 = fmaxf(acc[mt][nt][2] + bb0, 0.f);
                float v3 = fmaxf(acc[mt][nt][3] + bb1, 0.f);
                rs0[mt] = fmaf(v0, w30, fmaf(v1, w31, rs0[mt]));
                rs1[mt] = fmaf(v2, w30, fmaf(v3, w31, rs1[mt]));
            }
        }
    }

    #pragma unroll
    for (int mt = 0; mt < 2; mt++) {
        #pragma unroll
        for (int o = 1; o < 4; o <<= 1) {
            rs0[mt] += __shfl_xor_sync(0xffffffffu, rs0[mt], o);
            rs1[mt] += __shfl_xor_sync(0xffffffffu, rs1[mt], o);
        }
    }
    if ((lane & 3) == 0) {
        #pragma unroll
        for (int mt = 0; mt < 2; mt++) {
            int r_lo = row0 + wm + mt * 16 + (lane >> 2);
            if (r_lo < n)     atomicAdd(&g_xw3[r_lo], rs0[mt]);
            if (r_lo + 8 < n) atomicAdd(&g_xw3[r_lo + 8], rs1[mt]);
        }
    }
}

// ---------------- scalar aggregation of xw3 + fused BCE loss ----------------
__global__ void aggz_loss_kernel(const float* __restrict__ y, const float* __restrict__ b3,
                                 float* __restrict__ out, int n) {
    int i = blockIdx.x * blockDim.x + threadIdx.x;
    float l = 0.0f;
    if (i < n) {
        float di = g_dinv[i];
        float acc = di * di * g_xw3[i];
        int s0 = g_rowstart[i];
        int s1 = s0 + g_cnt[i];
        for (int j = s0; j < s1; j++) {
            int s = g_csr[j];
            acc = fmaf(g_dinv[s] * di, g_xw3[s], acc);
        }
        float z = acc + b3[0];
        float sp = fmaxf(z, 0.0f) + log1pf(expf(-fabsf(z)));
        l = sp - y[i] * z;
    }
    __shared__ float red[256];
    red[threadIdx.x] = l;
    __syncthreads();
    #pragma unroll
    for (int o = 128; o; o >>= 1) {
        if (threadIdx.x < o) red[threadIdx.x] += red[threadIdx.x + o];
        __syncthreads();
    }
    if (threadIdx.x == 0) atomicAdd(out, red[0] * (1.0f / (float)n));
}

// ---------------- launch ----------------
extern "C" void kernel_launch(void* const* d_in, const int* in_sizes, int n_in,
                              void* d_out, int out_size) {
    const float* x   = (const float*)d_in[0];
    const int*   ei  = (const int*)d_in[1];
    const float* y   = (const float*)d_in[2];
    const float* W1  = (const float*)d_in[3];
    const float* b1  = (const float*)d_in[4];
    const float* W2  = (const float*)d_in[5];
    const float* b2  = (const float*)d_in[6];
    const float* W3  = (const float*)d_in[7];
    const float* b3  = (const float*)d_in[8];
    float* out = (float*)d_out;

    int n = in_sizes[0] / F0;      // 100000
    int e = in_sizes[1] / 2;       // 1600000
    const int* src = ei;
    const int* dst = ei + e;

    static cudaStream_t s2 = nullptr;
    static cudaEvent_t evA = nullptr, evB = nullptr;
    if (!s2) {
        cudaStreamCreateWithFlags(&s2, cudaStreamNonBlocking);
        cudaEventCreateWithFlags(&evA, cudaEventDisableTiming);
        cudaEventCreateWithFlags(&evB, cudaEventDisableTiming);
        cudaFuncSetAttribute(fused_l2_kernel,
                             cudaFuncAttributeMaxDynamicSharedMemorySize, FL2_SMEM);
    }

    int nb = (n + 255) / 256;
    int nblk = (n + 127) / 128;    // 782

    // fork: gemm1 (x @ W1, independent of graph structure) on s2
    cudaEventRecord(evA, 0);
    cudaStreamWaitEvent(s2, evA, 0);
    gemm1_kernel<<<dim3(1, nblk), 256, 0, s2>>>(x, W1, n);
    cudaEventRecord(evB, s2);

    // stream 0: graph structure build
    init_kernel<<<nb, 256>>>(out, n);
    hist_kernel<<<(e + 255) / 256, 256>>>(dst, e);
    makecsr_kernel<<<nb, 256>>>(n);
    fill_kernel<<<(e + 255) / 256, 256>>>(src, dst, e);

    // join
    cudaStreamWaitEvent(0, evB, 0);

    // layer 1 aggregation (fused bias + relu)
    agg1_kernel<<<(n * 8 + 255) / 256, 256>>>(b1, n);

    // fused layer 2 + 3 front: agg(h1) @ W2 + b2, relu, dot W3 -> g_xw3
    fused_l2_kernel<<<nblk, 256, FL2_SMEM>>>(W2, b2, W3, n);

    // final: scalar aggregation + BCE loss
    aggz_loss_kernel<<<(n + 255) / 256, 256>>>(y, b3, out, n);
}

// round 16
// speedup vs baseline: 1.1264x; 1.0049x over previous
#include <cuda_runtime.h>
#include <cuda_bf16.h>
#include <cuda_fp8.h>
#include <math.h>
#include <stdint.h>

// ---------------- static problem sizes ----------------
#define NN  100000
#define EE  1600000
#define F0  512
#define D1  64
#define D2  256

// ---------------- device scratch ----------------
__device__ float g_dinv[NN];
__device__ int   g_cnt[NN];
__device__ int   g_rowstart[NN];
__device__ int   g_cursor[NN];
__device__ int   g_csr[EE];
__device__ int   g_edgetot;
__device__ uint16_t g_xw1[(size_t)NN * 32];   // fp8 e4m3 x2 per entry, 64B/row
__device__ uint16_t g_h1 [(size_t)NN * 32];   // fp8 e4m3 x2 per entry, 64B/row
__device__ float g_xw3[NN];

// ---------------- fp8 helpers ----------------
__device__ __forceinline__ uint16_t f2_to_fp8x2(float a, float b) {
    float2 f = make_float2(a, b);
    return __nv_cvt_float2_to_fp8x2(f, __NV_SATFINITE, __NV_E4M3);
}
__device__ __forceinline__ float2 fp8x2_to_f2(uint16_t v) {
    __half2_raw hr = __nv_cvt_fp8x2_to_halfraw2(v, __NV_E4M3);
    return __half22float2(*(__half2*)&hr);
}

// ---------------- init: zero counters + xw3 + output ----------------
__global__ void init_kernel(float* out, int n) {
    int i = blockIdx.x * blockDim.x + threadIdx.x;
    if (i < n) { g_cnt[i] = 0; g_xw3[i] = 0.0f; }
    if (i == 0) { out[0] = 0.0f; g_edgetot = 0; }
}

__global__ void hist_kernel(const int* __restrict__ dst, int e) {
    int i = blockIdx.x * blockDim.x + threadIdx.x;
    if (i < e) atomicAdd(&g_cnt[dst[i]], 1);
}

// ---------------- makecsr: dinv + segment allocation via warp-aggregated atomic ----
__global__ void makecsr_kernel(int n) {
    int i = blockIdx.x * 256 + threadIdx.x;
    int lane = threadIdx.x & 31;
    int v = (i < n) ? g_cnt[i] : 0;
    if (i < n) g_dinv[i] = rsqrtf((float)(v + 1));
    int x = v;
    #pragma unroll
    for (int o = 1; o < 32; o <<= 1) {
        int t = __shfl_up_sync(0xffffffffu, x, o);
        if (lane >= o) x += t;
    }
    int wsum = __shfl_sync(0xffffffffu, x, 31);
    int base = 0;
    if (lane == 31) base = atomicAdd(&g_edgetot, wsum);
    base = __shfl_sync(0xffffffffu, base, 31);
    if (i < n) {
        int rs = base + x - v;
        g_rowstart[i] = rs;
        g_cursor[i] = rs;
    }
}

__global__ void fill_kernel(const int* __restrict__ src, const int* __restrict__ dst, int e) {
    int i = blockIdx.x * blockDim.x + threadIdx.x;
    if (i < e) {
        int p = atomicAdd(&g_cursor[dst[i]], 1);
        g_csr[p] = src[i];
    }
}

// ---------------- tensor-core helpers ----------------
__device__ __forceinline__ uint32_t smem_u32(const void* p) {
    return (uint32_t)__cvta_generic_to_shared(p);
}
__device__ __forceinline__ void ldsm_x4(uint32_t& r0, uint32_t& r1, uint32_t& r2, uint32_t& r3, uint32_t a) {
    asm volatile("ldmatrix.sync.aligned.m8n8.x4.shared.b16 {%0,%1,%2,%3}, [%4];\n"
                 : "=r"(r0), "=r"(r1), "=r"(r2), "=r"(r3) : "r"(a));
}
__device__ __forceinline__ void ldsm_x4_t(uint32_t& r0, uint32_t& r1, uint32_t& r2, uint32_t& r3, uint32_t a) {
    asm volatile("ldmatrix.sync.aligned.m8n8.x4.trans.shared.b16 {%0,%1,%2,%3}, [%4];\n"
                 : "=r"(r0), "=r"(r1), "=r"(r2), "=r"(r3) : "r"(a));
}
__device__ __forceinline__ void mma_bf16(float* c, const uint32_t* a, const uint32_t* b) {
    asm volatile(
        "mma.sync.aligned.m16n8k16.row.col.f32.bf16.bf16.f32 "
        "{%0,%1,%2,%3}, {%4,%5,%6,%7}, {%8,%9}, {%0,%1,%2,%3};\n"
        : "+f"(c[0]), "+f"(c[1]), "+f"(c[2]), "+f"(c[3])
        : "r"(a[0]), "r"(a[1]), "r"(a[2]), "r"(a[3]), "r"(b[0]), "r"(b[1]));
}

// ---------------- gemm1: xw1 = x @ W1 (fp32 in, fp8 out), double-buffered smem ----
__global__ void __launch_bounds__(256)
gemm1_kernel(const float* __restrict__ A, const float* __restrict__ B, int M) {
    __shared__ __align__(16) __nv_bfloat16 As[2][128][72];
    __shared__ __align__(16) __nv_bfloat16 Bs[2][64][72];
    const int tid = threadIdx.x, lane = tid & 31, w = tid >> 5;
    const int wm = (w & 3) * 32, wn = (w >> 2) * 32;
    const int row0 = blockIdx.y * 128;

    float acc[2][4][4];
    #pragma unroll
    for (int mt = 0; mt < 2; mt++)
        #pragma unroll
        for (int nt = 0; nt < 4; nt++)
            #pragma unroll
            for (int r = 0; r < 4; r++) acc[mt][nt][r] = 0.0f;

    float4 a_f[8], b_f[4];
    auto load_regs = [&](int k0) {
        #pragma unroll
        for (int i = 0; i < 8; i++) {
            int idx = tid + i * 256;
            int r = idx >> 4, cq = idx & 15;
            int gr = row0 + r;
            a_f[i] = (gr < M) ? *(const float4*)&A[(size_t)gr * F0 + k0 + cq * 4]
                              : make_float4(0.f, 0.f, 0.f, 0.f);
        }
        #pragma unroll
        for (int i = 0; i < 4; i++) {
            int idx = tid + i * 256;
            int r = idx >> 4, cq = idx & 15;
            b_f[i] = *(const float4*)&B[(size_t)(k0 + r) * D1 + cq * 4];
        }
    };
    auto store_smem = [&](int buf) {
        #pragma unroll
        for (int i = 0; i < 8; i++) {
            int idx = tid + i * 256;
            int r = idx >> 4, cq = idx & 15;
            *(__nv_bfloat162*)&As[buf][r][cq * 4]     = __floats2bfloat162_rn(a_f[i].x, a_f[i].y);
            *(__nv_bfloat162*)&As[buf][r][cq * 4 + 2] = __floats2bfloat162_rn(a_f[i].z, a_f[i].w);
        }
        #pragma unroll
        for (int i = 0; i < 4; i++) {
            int idx = tid + i * 256;
            int r = idx >> 4, cq = idx & 15;
            *(__nv_bfloat162*)&Bs[buf][r][cq * 4]     = __floats2bfloat162_rn(b_f[i].x, b_f[i].y);
            *(__nv_bfloat162*)&Bs[buf][r][cq * 4 + 2] = __floats2bfloat162_rn(b_f[i].z, b_f[i].w);
        }
    };

    load_regs(0);
    store_smem(0);
    __syncthreads();
    int cur = 0;
    for (int k0 = 0; k0 < F0; k0 += 64) {
        bool more = (k0 + 64 < F0);
        if (more) load_regs(k0 + 64);
        #pragma unroll
        for (int ks = 0; ks < 4; ks++) {
            uint32_t a[2][4];
            #pragma unroll
            for (int mt = 0; mt < 2; mt++) {
                int rrow = wm + mt * 16 + (lane & 7) + ((lane >> 3) & 1) * 8;
                int ccol = ks * 16 + (lane >> 4) * 8;
                ldsm_x4(a[mt][0], a[mt][1], a[mt][2], a[mt][3], smem_u32(&As[cur][rrow][ccol]));
            }
            uint32_t b[4][2];
            #pragma unroll
            for (int pr = 0; pr < 2; pr++) {
                int kk = ks * 16 + ((lane >> 3) & 1) * 8 + (lane & 7);
                int nn = wn + pr * 16 + (lane >> 4) * 8;
                uint32_t r0, r1, r2, r3;
                ldsm_x4_t(r0, r1, r2, r3, smem_u32(&Bs[cur][kk][nn]));
                b[pr * 2][0] = r0; b[pr * 2][1] = r1;
                b[pr * 2 + 1][0] = r2; b[pr * 2 + 1][1] = r3;
            }
            #pragma unroll
            for (int mt = 0; mt < 2; mt++)
                #pragma unroll
                for (int nt = 0; nt < 4; nt++)
                    mma_bf16(acc[mt][nt], a[mt], b[nt]);
        }
        if (more) store_smem(cur ^ 1);
        __syncthreads();
        cur ^= 1;
    }
    // epilogue: fp8 e4m3 output (pairs)
    #pragma unroll
    for (int mt = 0; mt < 2; mt++) {
        int r_lo = row0 + wm + mt * 16 + (lane >> 2);
        #pragma unroll
        for (int nt = 0; nt < 4; nt++) {
            int c = wn + nt * 8 + (lane & 3) * 2;
            if (r_lo < M)
                g_xw1[(size_t)r_lo * 32 + (c >> 1)] =
                    f2_to_fp8x2(acc[mt][nt][0], acc[mt][nt][1]);
            if (r_lo + 8 < M)
                g_xw1[(size_t)(r_lo + 8) * 32 + (c >> 1)] =
                    f2_to_fp8x2(acc[mt][nt][2], acc[mt][nt][3]);
        }
    }
}

// ---------------- 64-dim gather-FMA core on fp8 rows (fp32 accum) ----------------
// one 8-lane group per node; each lane owns 8 consecutive fp8 (8B = uint2)
__device__ __forceinline__ void agg_row64_f8(float* acc, const uint2* in, int sub,
                                             float di, int s0, int s1) {
    for (int j = s0; j < s1; j++) {
        int s = __ldg(&g_csr[j]);
        float wgt = g_dinv[s] * di;
        uint2 v = in[(size_t)s * 8 + sub];
        const uint16_t* p = (const uint16_t*)&v;
        #pragma unroll
        for (int q = 0; q < 4; q++) {
            float2 f = fp8x2_to_f2(p[q]);
            acc[q * 2]     = fmaf(wgt, f.x, acc[q * 2]);
            acc[q * 2 + 1] = fmaf(wgt, f.y, acc[q * 2 + 1]);
        }
    }
}

// ---------------- layer 1 aggregation: h1 = relu(agg(xw1) + b1), fp8 out ----------
__global__ void agg1_kernel(const float* __restrict__ bias, int n) {
    int g = blockIdx.x * blockDim.x + threadIdx.x;
    int node = g >> 3;
    int sub  = g & 7;
    if (node >= n) return;
    const uint2* in = (const uint2*)g_xw1;
    float di = g_dinv[node];
    float w0 = di * di;
    float acc[8];
    {
        uint2 v = in[(size_t)node * 8 + sub];
        const uint16_t* p = (const uint16_t*)&v;
        #pragma unroll
        for (int q = 0; q < 4; q++) {
            float2 f = fp8x2_to_f2(p[q]);
            acc[q * 2]     = f.x * w0;
            acc[q * 2 + 1] = f.y * w0;
        }
    }
    int s0 = g_rowstart[node];
    agg_row64_f8(acc, in, sub, di, s0, s0 + g_cnt[node]);
    uint2 o;
    uint16_t* po = (uint16_t*)&o;
    #pragma unroll
    for (int q = 0; q < 4; q++) {
        float v0 = fmaxf(acc[q * 2]     + bias[sub * 8 + q * 2],     0.0f);
        float v1 = fmaxf(acc[q * 2 + 1] + bias[sub * 8 + q * 2 + 1], 0.0f);
        po[q] = f2_to_fp8x2(v0, v1);
    }
    ((uint2*)g_h1)[(size_t)node * 8 + sub] = o;
}

// ---------------- fused layer 2+3: agg(h1) -> @W2+b2, relu, dot W3 -> xw3 --------
#define FL2_AS_ROWS 128
#define FL2_AS_STRIDE 72
#define FL2_BS_STRIDE 264
#define FL2_SMEM (FL2_AS_ROWS * FL2_AS_STRIDE * 2 + 64 * FL2_BS_STRIDE * 2)  // 52224
__global__ void __launch_bounds__(256)
fused_l2_kernel(const float* __restrict__ W2, const float* __restrict__ b2,
                const float* __restrict__ W3, int n) {
    extern __shared__ char dynsmem[];
    __nv_bfloat16 (*As)[FL2_AS_STRIDE] = (__nv_bfloat16 (*)[FL2_AS_STRIDE])dynsmem;
    __nv_bfloat16 (*Bs)[FL2_BS_STRIDE] =
        (__nv_bfloat16 (*)[FL2_BS_STRIDE])(dynsmem + FL2_AS_ROWS * FL2_AS_STRIDE * 2);
    const int tid = threadIdx.x, lane = tid & 31, w = tid >> 5;
    const int wm = (w & 3) * 32, wn = (w >> 2) * 32;
    const int row0 = blockIdx.x * 128;

    // ---- stage ALL of W2 (64 x 256 fp32 -> bf16) ----
    #pragma unroll
    for (int i = 0; i < 16; i++) {
        int idx = tid + i * 256;
        int r = idx >> 6, cq = idx & 63;
        float4 v = *(const float4*)&W2[(size_t)r * D2 + cq * 4];
        *(__nv_bfloat162*)&Bs[r][cq * 4]     = __floats2bfloat162_rn(v.x, v.y);
        *(__nv_bfloat162*)&Bs[r][cq * 4 + 2] = __floats2bfloat162_rn(v.z, v.w);
    }

    // ---- prologue: aggregate 128 rows of fp8 h1 into bf16 As ----
    const uint2* in = (const uint2*)g_h1;
    #pragma unroll
    for (int it = 0; it < 4; it++) {
        int r = (tid >> 3) + it * 32;
        int sub = tid & 7;
        int node = row0 + r;
        float acc[8];
        #pragma unroll
        for (int q = 0; q < 8; q++) acc[q] = 0.0f;
        if (node < n) {
            float di = g_dinv[node];
            float w0 = di * di;
            uint2 v = in[(size_t)node * 8 + sub];
            const uint16_t* p = (const uint16_t*)&v;
            #pragma unroll
            for (int q = 0; q < 4; q++) {
                float2 f = fp8x2_to_f2(p[q]);
                acc[q * 2]     = f.x * w0;
                acc[q * 2 + 1] = f.y * w0;
            }
            int s0 = g_rowstart[node];
            agg_row64_f8(acc, in, sub, di, s0, s0 + g_cnt[node]);
        }
        uint4 o;
        uint32_t* po = (uint32_t*)&o;
        #pragma unroll
        for (int q = 0; q < 4; q++)
            *(__nv_bfloat162*)&po[q] = __floats2bfloat162_rn(acc[q * 2], acc[q * 2 + 1]);
        *(uint4*)&As[r][sub * 8] = o;
    }
    __syncthreads();   // the ONLY barrier

    // ---- hoist A fragments ----
    uint32_t afrag[4][2][4];
    #pragma unroll
    for (int ks = 0; ks < 4; ks++) {
        #pragma unroll
        for (int mt = 0; mt < 2; mt++) {
            int rrow = wm + mt * 16 + (lane & 7) + ((lane >> 3) & 1) * 8;
            int ccol = ks * 16 + (lane >> 4) * 8;
            ldsm_x4(afrag[ks][mt][0], afrag[ks][mt][1], afrag[ks][mt][2], afrag[ks][mt][3],
                    smem_u32(&As[rrow][ccol]));
        }
    }

    float rs0[2], rs1[2];
    rs0[0] = rs0[1] = rs1[0] = rs1[1] = 0.0f;

    #pragma unroll
    for (int ch = 0; ch < 4; ch++) {
        int cols0 = ch * 64;
        float acc[2][4][4];
        #pragma unroll
        for (int mt = 0; mt < 2; mt++)
            #pragma unroll
            for (int nt = 0; nt < 4; nt++)
                #pragma unroll
                for (int r = 0; r < 4; r++) acc[mt][nt][r] = 0.0f;

        #pragma unroll
        for (int ks = 0; ks < 4; ks++) {
            uint32_t b[4][2];
            #pragma unroll
            for (int pr = 0; pr < 2; pr++) {
                int kk = ks * 16 + ((lane >> 3) & 1) * 8 + (lane & 7);
                int nn = cols0 + wn + pr * 16 + (lane >> 4) * 8;
                uint32_t r0, r1, r2, r3;
                ldsm_x4_t(r0, r1, r2, r3, smem_u32(&Bs[kk][nn]));
                b[pr * 2][0] = r0; b[pr * 2][1] = r1;
                b[pr * 2 + 1][0] = r2; b[pr * 2 + 1][1] = r3;
            }
            #pragma unroll
            for (int mt = 0; mt < 2; mt++)
                #pragma unroll
                for (int nt = 0; nt < 4; nt++)
                    mma_bf16(acc[mt][nt], afrag[ks][mt], b[nt]);
        }
        #pragma unroll
        for (int mt = 0; mt < 2; mt++) {
            #pragma unroll
            for (int nt = 0; nt < 4; nt++) {
                int c = cols0 + wn + nt * 8 + (lane & 3) * 2;
                float bb0 = b2[c], bb1 = b2[c + 1];
                float w30 = W3[c], w31 = W3[c + 1];
                float v0 = fmaxf(acc[mt][nt][0] + bb0, 0.f);
                float v1 = fmaxf(acc[mt][nt][1] + bb1, 0.f);
                float v2 = fmaxf(acc[mt][nt][2] + bb0, 0.f);
                float v3 = fmaxf(acc[mt][nt][3] + bb1, 0.f);
                rs0[mt] = fmaf(v0, w30, fmaf(v1, w31, rs0[mt]));
                rs1[mt] = fmaf(v2, w30, fmaf(v3, w31, rs1[mt]));
            }
        }
    }

    #pragma unroll
    for (int mt = 0; mt < 2; mt++) {
        #pragma unroll
        for (int o = 1; o < 4; o <<= 1) {
            rs0[mt] += __shfl_xor_sync(0xffffffffu, rs0[mt], o);
            rs1[mt] += __shfl_xor_sync(0xffffffffu, rs1[mt], o);
        }
    }
    if ((lane & 3) == 0) {
        #pragma unroll
        for (int mt = 0; mt < 2; mt++) {
            int r_lo = row0 + wm + mt * 16 + (lane >> 2);
            if (r_lo < n)     atomicAdd(&g_xw3[r_lo], rs0[mt]);
            if (r_lo + 8 < n) atomicAdd(&g_xw3[r_lo + 8], rs1[mt]);
        }
    }
}

// ---------------- scalar aggregation of xw3 + fused BCE loss ----------------
__global__ void aggz_loss_kernel(const float* __restrict__ y, const float* __restrict__ b3,
                                 float* __restrict__ out, int n) {
    int i = blockIdx.x * blockDim.x + threadIdx.x;
    float l = 0.0f;
    if (i < n) {
        float di = g_dinv[i];
        float acc = di * di * g_xw3[i];
        int s0 = g_rowstart[i];
        int s1 = s0 + g_cnt[i];
        for (int j = s0; j < s1; j++) {
            int s = g_csr[j];
            acc = fmaf(g_dinv[s] * di, g_xw3[s], acc);
        }
        float z = acc + b3[0];
        float sp = fmaxf(z, 0.0f) + log1pf(expf(-fabsf(z)));
        l = sp - y[i] * z;
    }
    __shared__ float red[256];
    red[threadIdx.x] = l;
    __syncthreads();
    #pragma unroll
    for (int o = 128; o; o >>= 1) {
        if (threadIdx.x < o) red[threadIdx.x] += red[threadIdx.x + o];
        __syncthreads();
    }
    if (threadIdx.x == 0) atomicAdd(out, red[0] * (1.0f / (float)n));
}

// ---------------- launch ----------------
extern "C" void kernel_launch(void* const* d_in, const int* in_sizes, int n_in,
                              void* d_out, int out_size) {
    const float* x   = (const float*)d_in[0];
    const int*   ei  = (const int*)d_in[1];
    const float* y   = (const float*)d_in[2];
    const float* W1  = (const float*)d_in[3];
    const float* b1  = (const float*)d_in[4];
    const float* W2  = (const float*)d_in[5];
    const float* b2  = (const float*)d_in[6];
    const float* W3  = (const float*)d_in[7];
    const float* b3  = (const float*)d_in[8];
    float* out = (float*)d_out;

    int n = in_sizes[0] / F0;      // 100000
    int e = in_sizes[1] / 2;       // 1600000
    const int* src = ei;
    const int* dst = ei + e;

    static cudaStream_t s2 = nullptr;
    static cudaEvent_t evA = nullptr, evB = nullptr;
    if (!s2) {
        cudaStreamCreateWithFlags(&s2, cudaStreamNonBlocking);
        cudaEventCreateWithFlags(&evA, cudaEventDisableTiming);
        cudaEventCreateWithFlags(&evB, cudaEventDisableTiming);
        cudaFuncSetAttribute(fused_l2_kernel,
                             cudaFuncAttributeMaxDynamicSharedMemorySize, FL2_SMEM);
    }

    int nb = (n + 255) / 256;
    int nblk = (n + 127) / 128;    // 782

    // fork: gemm1 (x @ W1, independent of graph structure) on s2
    cudaEventRecord(evA, 0);
    cudaStreamWaitEvent(s2, evA, 0);
    gemm1_kernel<<<dim3(1, nblk), 256, 0, s2>>>(x, W1, n);
    cudaEventRecord(evB, s2);

    // stream 0: graph structure build
    init_kernel<<<nb, 256>>>(out, n);
    hist_kernel<<<(e + 255) / 256, 256>>>(dst, e);
    makecsr_kernel<<<nb, 256>>>(n);
    fill_kernel<<<(e + 255) / 256, 256>>>(src, dst, e);

    // join
    cudaStreamWaitEvent(0, evB, 0);

    // layer 1 aggregation (fused bias + relu)
    agg1_kernel<<<(n * 8 + 255) / 256, 256>>>(b1, n);

    // fused layer 2 + 3 front: agg(h1) @ W2 + b2, relu, dot W3 -> g_xw3
    fused_l2_kernel<<<nblk, 256, FL2_SMEM>>>(W2, b2, W3, n);

    // final: scalar aggregation + BCE loss
    aggz_loss_kernel<<<(n + 255) / 256, 256>>>(y, b3, out, n);
}